// round 3
// baseline (speedup 1.0000x reference)
#include <cuda_runtime.h>
#include <cuda_bf16.h>
#include <math.h>
#include <stdint.h>

// ---------------- problem constants ----------------
#define B_  32
#define L_  1024
#define DIN 16
#define DM  512
#define DI  1024          // EXP*DM
#define H_  16            // DI/P
#define P_  64
#define N_  64
#define DCONV 4
#define CONV_DIM 1152     // DI + 2N
#define DPROJ 2192        // 2*DI + 2*N + H
#define REST 1168         // CONV_DIM + H  (columns DI..DPROJ of Win)
#define NCLS 10
#define BL  (B_*L_)       // 32768
#define EPS 1e-5f

// ---------------- scratch (static device globals; no allocations) -------------
__device__ float g_h1[BL*128];
__device__ float g_h2[BL*256];
__device__ float g_u [BL*DM];
__device__ float g_xbcr[(size_t)BL*REST];   // cols DI..DPROJ of zxbcdt
__device__ float g_xs [(size_t)BL*DI];      // conv output, first DI channels
__device__ float g_Bm [BL*N_];
__device__ float g_Cm [B_*N_];              // C at l = L-1 only
__device__ float g_dtp[B_*H_*L_];           // softplus(dt + bias), layout [b*H+h][l]
__device__ float g_coef[B_*H_*L_];          // exp(-a*suffix)*dt
__device__ float g_beta[BL];                // B_t . C_last
__device__ float g_y  [B_*DI];
__device__ float g_z  [B_*DI];              // z at l = L-1

// =============================================================================
// TF32 tensor-core GEMM, fragment-major smem staging.
// A: MxK row-major (lda), W: KxN row-major (ldw), C: MxN (ldc)
// M % 128 == 0, K % 16 == 0.  Block tile 128x128, BK=16, double buffered.
// 256 threads = 8 warps (2m x 4n), warp tile 64x32, mma m16n8k8.
// Smem layout stores operands in EXACT mma fragment order:
//   A value A[m][kk] (kk in 0..15):
//     ks=kk>>3, mb=m>>4, reg=((m>>3)&1)+2*(((kk&7))>=4), lane=(m&7)*4+(kk&3)
//     word = (ks*8+mb)*128 + (lane&3)*32 + (lane>>2)*4 + reg      (lane-rotated)
//   B value B[kk][n]:
//     ks=kk>>3, nb=n>>3, reg=((kk&7))>=4, lane=(n&7)*4+(kk&3)
//     word = (ks*16+nb)*66 + lane*2 + reg                          (+2 word pad)
// Consumption: A = one LDS.128 per (ks,mb); B = one LDS.64 per (ks,nb).
// =============================================================================
__device__ __forceinline__ uint32_t f2tf32(float f) {
    uint32_t u;
    asm volatile("cvt.rna.tf32.f32 %0, %1;" : "=r"(u) : "f"(f));
    return u;
}
__device__ __forceinline__ void mma_tf32(float* c, const uint32_t* a, const uint32_t* b) {
    asm volatile(
        "mma.sync.aligned.m16n8k8.row.col.f32.tf32.tf32.f32 "
        "{%0,%1,%2,%3}, {%4,%5,%6,%7}, {%8,%9}, {%0,%1,%2,%3};\n"
        : "+f"(c[0]), "+f"(c[1]), "+f"(c[2]), "+f"(c[3])
        : "r"(a[0]), "r"(a[1]), "r"(a[2]), "r"(a[3]), "r"(b[0]), "r"(b[1]));
}

#define AWORDS 2048   // 16 blocks * 128 words
#define BWORDS 2112   // 32 blocks * 66 words

__device__ __forceinline__ void stageA(uint32_t* As_s, int m, int kq, float4 v) {
    int ks  = kq >> 1;
    int mb  = m >> 4;
    int reg = ((m >> 3) & 1) + ((kq & 1) << 1);
    uint32_t* p = As_s + (ks * 8 + mb) * 128 + (m & 7) * 4 + reg;
    p[0]  = f2tf32(v.x);
    p[32] = f2tf32(v.y);
    p[64] = f2tf32(v.z);
    p[96] = f2tf32(v.w);
}
__device__ __forceinline__ void stageB(uint32_t* Bs_s, int k, int n4, float4 v) {
    int ks   = k >> 3;
    int k8   = k & 7;
    int reg  = k8 >> 2;
    int k3   = k8 & 3;
    int nb   = n4 >> 3;
    int nlow = n4 & 7;   // 0 or 4
    uint32_t* p = Bs_s + (ks * 16 + nb) * 66 + nlow * 8 + k3 * 2 + reg;
    p[0]  = f2tf32(v.x);
    p[8]  = f2tf32(v.y);
    p[16] = f2tf32(v.z);
    p[24] = f2tf32(v.w);
}

template<int RELU>
__global__ __launch_bounds__(256, 2) void tgemm_kernel(
    const float* __restrict__ A, int lda,
    const float* __restrict__ W, int ldw,
    const float* __restrict__ bias,
    float* __restrict__ C, int ldc,
    int N, int K)
{
    __shared__ uint32_t As[2][AWORDS];
    __shared__ uint32_t Bs[2][BWORDS];

    const int bm = blockIdx.y * 128;
    const int bn = blockIdx.x * 128;
    const int tid = threadIdx.x;
    const int warp = tid >> 5;
    const int lane = tid & 31;
    const int warp_m = (warp & 1) * 64;     // row offset
    const int warp_n = (warp >> 1) * 32;    // col offset
    const int warp_mb = (warp & 1) * 4;     // A block index base
    const int warp_nb = (warp >> 1) * 4;    // B block index base
    const int lg = lane >> 2;
    const int lr = lane & 3;
    const int alane = ((lane & 3) << 5) + ((lane >> 2) << 2);  // rotated word offset

    // gmem load coords
    const int am  = tid >> 2;            // 0..63 (also handles am+64)
    const int akq = tid & 3;             // k-quad
    const int bk  = tid >> 5;            // 0..7 (also bk+8)
    const int bn4 = (tid & 31) * 4;      // 0..124

    float acc[4][4][4];
    #pragma unroll
    for (int i = 0; i < 4; i++)
        #pragma unroll
        for (int j = 0; j < 4; j++)
            #pragma unroll
            for (int r = 0; r < 4; r++) acc[i][j][r] = 0.f;

    const int T = K >> 4;
    float4 ar0, ar1, br0, br1;

    // ---- global load of tile t into registers ----
    auto gload = [&](int t) {
        const int k0 = t * 16;
        ar0 = *(const float4*)&A[(size_t)(bm + am)      * lda + k0 + akq * 4];
        ar1 = *(const float4*)&A[(size_t)(bm + am + 64) * lda + k0 + akq * 4];
        int n = bn + bn4;
        const float* wr0 = W + (size_t)(k0 + bk) * ldw;
        const float* wr1 = W + (size_t)(k0 + bk + 8) * ldw;
        if (n + 3 < N) {
            br0 = *(const float4*)&wr0[n];
            br1 = *(const float4*)&wr1[n];
        } else {
            br0.x = (n     < N) ? wr0[n]     : 0.f;
            br0.y = (n + 1 < N) ? wr0[n + 1] : 0.f;
            br0.z = (n + 2 < N) ? wr0[n + 2] : 0.f;
            br0.w = (n + 3 < N) ? wr0[n + 3] : 0.f;
            br1.x = (n     < N) ? wr1[n]     : 0.f;
            br1.y = (n + 1 < N) ? wr1[n + 1] : 0.f;
            br1.z = (n + 2 < N) ? wr1[n + 2] : 0.f;
            br1.w = (n + 3 < N) ? wr1[n + 3] : 0.f;
        }
    };
    auto sstore = [&](int s) {
        stageA(As[s], am,      akq, ar0);
        stageA(As[s], am + 64, akq, ar1);
        stageB(Bs[s], bk,     bn4, br0);
        stageB(Bs[s], bk + 8, bn4, br1);
    };

    gload(0);
    sstore(0);
    __syncthreads();

    for (int t = 0; t < T; t++) {
        const int s = t & 1;
        if (t + 1 < T) gload(t + 1);

        #pragma unroll
        for (int ks = 0; ks < 2; ks++) {
            uint32_t af[4][4], bf[4][2];
            const uint32_t* Ab = &As[s][ks * 8 * 128];
            const uint32_t* Bb = &Bs[s][ks * 16 * 66];
            #pragma unroll
            for (int mi = 0; mi < 4; mi++) {
                uint4 a = *(const uint4*)&Ab[(warp_mb + mi) * 128 + alane];
                af[mi][0] = a.x; af[mi][1] = a.y; af[mi][2] = a.z; af[mi][3] = a.w;
            }
            #pragma unroll
            for (int ni = 0; ni < 4; ni++) {
                uint2 b = *(const uint2*)&Bb[(warp_nb + ni) * 66 + lane * 2];
                bf[ni][0] = b.x; bf[ni][1] = b.y;
            }
            #pragma unroll
            for (int mi = 0; mi < 4; mi++)
                #pragma unroll
                for (int ni = 0; ni < 4; ni++)
                    mma_tf32(acc[mi][ni], af[mi], bf[ni]);
        }

        if (t + 1 < T) {
            __syncthreads();     // ensure all reads of stage s^1 done before overwrite
            sstore(s ^ 1);
        }
        __syncthreads();
    }

    // ---- epilogue ----
    #pragma unroll
    for (int mi = 0; mi < 4; mi++) {
        #pragma unroll
        for (int half = 0; half < 2; half++) {
            const int gr = bm + warp_m + mi * 16 + lg + half * 8;
            #pragma unroll
            for (int ni = 0; ni < 4; ni++) {
                const int gn = bn + warp_n + ni * 8 + lr * 2;
                if (gn >= N) continue;
                float v0 = acc[mi][ni][half * 2 + 0];
                float v1 = acc[mi][ni][half * 2 + 1];
                if (bias) { v0 += bias[gn]; v1 += bias[gn + 1]; }
                if (RELU) { v0 = fmaxf(v0, 0.f); v1 = fmaxf(v1, 0.f); }
                *(float2*)&C[(size_t)gr * ldc + gn] = make_float2(v0, v1);
            }
        }
    }
}

// ---------------- generic tiled SGEMM (tiny GEMMs) ----------------------------
template<int RELU>
__global__ void sgemm_kernel(const float* __restrict__ A, int lda,
                             const float* __restrict__ W, int ldw,
                             const float* __restrict__ bias,
                             float* __restrict__ C, int ldc,
                             int M, int N, int K)
{
    __shared__ float As[8][128];
    __shared__ float Bs[8][128];
    const int bm = blockIdx.y * 128;
    const int bn = blockIdx.x * 128;
    const int tid = threadIdx.x;
    const int tr = tid >> 4;
    const int tc = tid & 15;

    float acc[8][8];
    #pragma unroll
    for (int i = 0; i < 8; i++)
        #pragma unroll
        for (int j = 0; j < 8; j++) acc[i][j] = 0.f;

    for (int k0 = 0; k0 < K; k0 += 8) {
        {
            int e = tid * 4;
            int r = e >> 3, kk = e & 7;
            int gr = bm + r;
            float4 av = make_float4(0.f, 0.f, 0.f, 0.f);
            if (gr < M) av = *(const float4*)&A[(size_t)gr * lda + k0 + kk];
            As[kk + 0][r] = av.x; As[kk + 1][r] = av.y;
            As[kk + 2][r] = av.z; As[kk + 3][r] = av.w;
        }
        {
            int e = tid * 4;
            int kk = e >> 7, n = e & 127;
            const float* wrow = W + (size_t)(k0 + kk) * ldw;
            #pragma unroll
            for (int i = 0; i < 4; i++) {
                int gn = bn + n + i;
                Bs[kk][n + i] = (gn < N) ? wrow[gn] : 0.f;
            }
        }
        __syncthreads();
        #pragma unroll
        for (int kk = 0; kk < 8; kk++) {
            float4 a0 = *(const float4*)&As[kk][tr * 4];
            float4 a1 = *(const float4*)&As[kk][64 + tr * 4];
            float4 b0 = *(const float4*)&Bs[kk][tc * 4];
            float4 b1 = *(const float4*)&Bs[kk][64 + tc * 4];
            float a[8] = {a0.x,a0.y,a0.z,a0.w,a1.x,a1.y,a1.z,a1.w};
            float b[8] = {b0.x,b0.y,b0.z,b0.w,b1.x,b1.y,b1.z,b1.w};
            #pragma unroll
            for (int i = 0; i < 8; i++)
                #pragma unroll
                for (int j = 0; j < 8; j++) acc[i][j] = fmaf(a[i], b[j], acc[i][j]);
        }
        __syncthreads();
    }
    #pragma unroll
    for (int i = 0; i < 8; i++) {
        int gr = bm + ((i < 4) ? (tr * 4 + i) : (64 + tr * 4 + i - 4));
        if (gr >= M) continue;
        #pragma unroll
        for (int j = 0; j < 8; j++) {
            int gn = bn + ((j < 4) ? (tc * 4 + j) : (64 + tc * 4 + j - 4));
            if (gn >= N) continue;
            float v = acc[i][j];
            if (bias) v += bias[gn];
            if (RELU) v = fmaxf(v, 0.f);
            C[(size_t)gr * ldc + gn] = v;
        }
    }
}

// ---------------- depthwise causal conv (time-marching) + silu + softplus -----
__device__ __forceinline__ float siluf(float x) { return x / (1.f + __expf(-x)); }
__device__ __forceinline__ float softplusf(float x) {
    return (x > 0.f) ? x + log1pf(__expf(-x)) : log1pf(__expf(x));
}

#define LCH 128   // time chunk per block-z

__global__ void conv_kernel(const float* __restrict__ xbcr,   // [BL, REST]
                            const float* __restrict__ conv_w, // [1152,4]
                            const float* __restrict__ conv_b, // [1152]
                            const float* __restrict__ dt_bias,// [16]
                            float* __restrict__ xs, float* __restrict__ Bm,
                            float* __restrict__ Cm, float* __restrict__ dtp)
{
    int c  = blockIdx.x * blockDim.x + threadIdx.x;
    int b  = blockIdx.y;
    int l0 = blockIdx.z * LCH;
    if (c >= REST) return;
    const float* col = xbcr + (size_t)b * L_ * REST + c;

    if (c >= CONV_DIM) {
        int h = c - CONV_DIM;
        float bias = dt_bias[h];
        float* drow = dtp + (size_t)(b * H_ + h) * L_;
        #pragma unroll 4
        for (int l = l0; l < l0 + LCH; l++)
            drow[l] = softplusf(col[(size_t)l * REST] + bias);
        return;
    }

    float w0 = conv_w[c * 4 + 0], w1 = conv_w[c * 4 + 1];
    float w2 = conv_w[c * 4 + 2], w3 = conv_w[c * 4 + 3];
    float cb = conv_b[c];

    if (c >= DI + N_) {
        // C channels: only l = L-1 matters (handled by last chunk)
        if (l0 + LCH != L_) return;
        int l = L_ - 1;
        float acc = cb + w0 * col[(size_t)(l - 3) * REST] + w1 * col[(size_t)(l - 2) * REST]
                       + w2 * col[(size_t)(l - 1) * REST] + w3 * col[(size_t)l * REST];
        Cm[b * N_ + (c - DI - N_)] = siluf(acc);
        return;
    }

    float xm3 = (l0 - 3 >= 0) ? col[(size_t)(l0 - 3) * REST] : 0.f;
    float xm2 = (l0 - 2 >= 0) ? col[(size_t)(l0 - 2) * REST] : 0.f;
    float xm1 = (l0 - 1 >= 0) ? col[(size_t)(l0 - 1) * REST] : 0.f;
    if (c < DI) {
        float* orow = xs + (size_t)(b * L_ + l0) * DI + c;
        #pragma unroll 4
        for (int l = l0; l < l0 + LCH; l++) {
            float xl = col[(size_t)l * REST];
            float acc = fmaf(w0, xm3, fmaf(w1, xm2, fmaf(w2, xm1, fmaf(w3, xl, cb))));
            *orow = siluf(acc);
            orow += DI;
            xm3 = xm2; xm2 = xm1; xm1 = xl;
        }
    } else {
        float* orow = Bm + (size_t)(b * L_ + l0) * N_ + (c - DI);
        #pragma unroll 4
        for (int l = l0; l < l0 + LCH; l++) {
            float xl = col[(size_t)l * REST];
            float acc = fmaf(w0, xm3, fmaf(w1, xm2, fmaf(w2, xm1, fmaf(w3, xl, cb))));
            *orow = siluf(acc);
            orow += N_;
            xm3 = xm2; xm2 = xm1; xm1 = xl;
        }
    }
}

// ---------------- suffix-sum of dt and coefficient exp(-a*S)*dt ---------------
__global__ void scan_kernel(const float* __restrict__ dtp,
                            const float* __restrict__ A_log,
                            float* __restrict__ coef)
{
    int bh = blockIdx.x;
    int h = bh & (H_ - 1);
    float a = expf(A_log[h]);
    __shared__ float part[256];
    __shared__ float off[256];
    const float* row = dtp + (size_t)bh * L_;
    int t0 = threadIdx.x * 4;
    float v0 = row[t0], v1 = row[t0 + 1], v2 = row[t0 + 2], v3 = row[t0 + 3];
    part[threadIdx.x] = v0 + v1 + v2 + v3;
    __syncthreads();
    if (threadIdx.x == 0) {
        float s = 0.f;
        for (int i = 255; i >= 0; i--) { off[i] = s; s += part[i]; }
    }
    __syncthreads();
    float S3 = off[threadIdx.x];
    float S2 = S3 + v3;
    float S1 = S2 + v2;
    float S0 = S1 + v1;
    float* out = coef + (size_t)bh * L_;
    out[t0 + 0] = expf(-a * S0) * v0;
    out[t0 + 1] = expf(-a * S1) * v1;
    out[t0 + 2] = expf(-a * S2) * v2;
    out[t0 + 3] = expf(-a * S3) * v3;
}

// ---------------- beta[b,t] = B_t . C_last -----------------------------------
__global__ void beta_kernel(const float* __restrict__ Bm,
                            const float* __restrict__ Cm,
                            float* __restrict__ beta)
{
    int row = blockIdx.x;
    int b = row >> 10;
    int lane = threadIdx.x;
    float s = Bm[(size_t)row * N_ + lane]      * Cm[b * N_ + lane]
            + Bm[(size_t)row * N_ + 32 + lane] * Cm[b * N_ + 32 + lane];
    #pragma unroll
    for (int o = 16; o; o >>= 1) s += __shfl_down_sync(0xffffffffu, s, o);
    if (lane == 0) beta[row] = s;
}

// ---------------- y[b,h,p] = sum_t coef*beta*xs + D*xs_last -------------------
__global__ void y_kernel(const float* __restrict__ xs,
                         const float* __restrict__ coef,
                         const float* __restrict__ beta,
                         const float* __restrict__ D,
                         float* __restrict__ y)
{
    int bh = blockIdx.x;
    int b = bh >> 4, h = bh & (H_ - 1);
    int tid = threadIdx.x;                // 512 threads
    int tq = tid >> 6;
    int p  = tid & 63;
    __shared__ float w[L_];
    __shared__ float partial[8][64];
    const float* crow = coef + (size_t)bh * L_;
    const float* brow = beta + (size_t)b * L_;
    for (int i = tid; i < L_; i += 512) w[i] = crow[i] * brow[i];
    __syncthreads();
    const float* xbase = xs + (size_t)b * L_ * DI + h * P_ + p;
    float acc = 0.f;
    const int t0 = tq * 128;
    #pragma unroll 4
    for (int t = t0; t < t0 + 128; t++)
        acc = fmaf(w[t], xbase[(size_t)t * DI], acc);
    partial[tq][p] = acc;
    __syncthreads();
    if (tq == 0) {
        float s = 0.f;
        #pragma unroll
        for (int q = 0; q < 8; q++) s += partial[q][p];
        s = fmaf(D[h], xbase[(size_t)(L_ - 1) * DI], s);
        y[bh * P_ + p] = s;
    }
}

// ---------------- gate + rmsnorm + Wout + Wc head -----------------------------
__global__ void final_kernel(const float* __restrict__ y,
                             const float* __restrict__ zlast,
                             const float* __restrict__ norm_w,
                             const float* __restrict__ Wout,
                             const float* __restrict__ Wc,
                             const float* __restrict__ bc,
                             float* __restrict__ out)
{
    int b = blockIdx.x;
    int tid = threadIdx.x;                // 256
    __shared__ float yn[DI];
    __shared__ float seq[DM];
    __shared__ float red[256];
    float ss = 0.f;
    for (int d = tid; d < DI; d += 256) {
        float z = zlast[b * DI + d];
        float g = y[b * DI + d] * (z / (1.f + __expf(-z)));
        yn[d] = g;
        ss += g * g;
    }
    red[tid] = ss; __syncthreads();
    for (int o = 128; o; o >>= 1) { if (tid < o) red[tid] += red[tid + o]; __syncthreads(); }
    float scale = rsqrtf(red[0] / (float)DI + EPS);
    for (int d = tid; d < DI; d += 256) yn[d] *= scale * norm_w[d];
    __syncthreads();
    for (int m = tid; m < DM; m += 256) {
        float accm = 0.f;
        for (int d = 0; d < DI; d++) accm = fmaf(yn[d], Wout[(size_t)d * DM + m], accm);
        seq[m] = accm;
    }
    __syncthreads();
    if (tid < NCLS) {
        float acc = bc[tid];
        for (int m = 0; m < DM; m++) acc = fmaf(seq[m], Wc[m * NCLS + tid], acc);
        out[b * NCLS + tid] = acc;
    }
}

// ---------------- launch ------------------------------------------------------
extern "C" void kernel_launch(void* const* d_in, const int* in_sizes, int n_in,
                              void* d_out, int out_size)
{
    const float* x       = (const float*)d_in[0];
    const float* W1      = (const float*)d_in[1];
    const float* b1      = (const float*)d_in[2];
    const float* W2      = (const float*)d_in[3];
    const float* b2      = (const float*)d_in[4];
    const float* W3      = (const float*)d_in[5];
    const float* b3      = (const float*)d_in[6];
    const float* Win     = (const float*)d_in[7];
    const float* conv_w  = (const float*)d_in[8];
    const float* conv_b  = (const float*)d_in[9];
    const float* dt_bias = (const float*)d_in[10];
    const float* A_log   = (const float*)d_in[11];
    const float* Dv      = (const float*)d_in[12];
    const float* norm_w  = (const float*)d_in[13];
    const float* Wout    = (const float*)d_in[14];
    const float* Wc      = (const float*)d_in[15];
    const float* bc      = (const float*)d_in[16];
    float* out = (float*)d_out;

    float *h1, *h2, *u, *xbcr, *xs, *Bm, *Cm, *dtp, *coef, *beta, *yb, *zb;
    cudaGetSymbolAddress((void**)&h1,   g_h1);
    cudaGetSymbolAddress((void**)&h2,   g_h2);
    cudaGetSymbolAddress((void**)&u,    g_u);
    cudaGetSymbolAddress((void**)&xbcr, g_xbcr);
    cudaGetSymbolAddress((void**)&xs,   g_xs);
    cudaGetSymbolAddress((void**)&Bm,   g_Bm);
    cudaGetSymbolAddress((void**)&Cm,   g_Cm);
    cudaGetSymbolAddress((void**)&dtp,  g_dtp);
    cudaGetSymbolAddress((void**)&coef, g_coef);
    cudaGetSymbolAddress((void**)&beta, g_beta);
    cudaGetSymbolAddress((void**)&yb,   g_y);
    cudaGetSymbolAddress((void**)&zb,   g_z);

    // G1: x -> 128 (K=16, fp32 fma)
    sgemm_kernel<1><<<dim3(1, BL/128), 256>>>(x, DIN, W1, 128, b1, h1, 128, BL, 128, DIN);
    // G2: 128 -> 256 (tf32)
    tgemm_kernel<1><<<dim3(2, BL/128), 256>>>(h1, 128, W2, 256, b2, h2, 256, 256, 128);
    // G3: 256 -> 512 (tf32)
    tgemm_kernel<0><<<dim3(4, BL/128), 256>>>(h2, 256, W3, DM, b3, u, DM, DM, 256);
    // G4: u @ Win[:, DI:DPROJ] (tf32), N=1168
    tgemm_kernel<0><<<dim3(10, BL/128), 256>>>(u, DM, Win + DI, DPROJ, nullptr,
                                               xbcr, REST, REST, DM);
    // G5: z at last position only (32 rows, fp32)
    sgemm_kernel<0><<<dim3(DI/128, 1), 256>>>(u + (size_t)(L_-1)*DM, L_*DM, Win, DPROJ, nullptr,
                                              zb, DI, B_, DI, DM);
    // conv + silu + softplus(dt), time-marching
    conv_kernel<<<dim3((REST+255)/256, B_, L_/LCH), 256>>>(xbcr, conv_w, conv_b, dt_bias,
                                                           xs, Bm, Cm, dtp);
    // suffix scan -> coefficients
    scan_kernel<<<B_*H_, 256>>>(dtp, A_log, coef);
    // beta
    beta_kernel<<<BL, 32>>>(Bm, Cm, beta);
    // y reduction over time
    y_kernel<<<B_*H_, 512>>>(xs, coef, beta, Dv, yb);
    // head
    final_kernel<<<B_, 256>>>(yb, zb, norm_w, Wout, Wc, bc, out);
    (void)in_sizes; (void)n_in; (void)out_size;
}

// round 4
// speedup vs baseline: 1.2434x; 1.2434x over previous
#include <cuda_runtime.h>
#include <cuda_bf16.h>
#include <math.h>
#include <stdint.h>

// ---------------- problem constants ----------------
#define B_  32
#define L_  1024
#define DIN 16
#define DM  512
#define DI  1024          // EXP*DM
#define H_  16            // DI/P
#define P_  64
#define N_  64
#define DCONV 4
#define CONV_DIM 1152     // DI + 2N
#define DPROJ 2192        // 2*DI + 2*N + H
#define REST 1168         // CONV_DIM + H  (columns DI..DPROJ of Win)
#define NCLS 10
#define BL  (B_*L_)       // 32768
#define EPS 1e-5f

// ---------------- scratch (static device globals; no allocations) -------------
__device__ float g_h1[BL*128];
__device__ float g_h2[BL*256];
__device__ float g_u [BL*DM];
__device__ float g_xbcr[(size_t)BL*REST];   // cols DI..DPROJ of zxbcdt
__device__ float g_xs [(size_t)BL*DI];      // conv output, first DI channels
__device__ float g_Bm [BL*N_];
__device__ float g_Cm [B_*N_];              // C at l = L-1 only
__device__ float g_dtp[B_*H_*L_];           // softplus(dt + bias), layout [b*H+h][l]
__device__ float g_coef[B_*H_*L_];          // exp(-a*suffix)*dt
__device__ float g_beta[BL];                // B_t . C_last
__device__ float g_y  [B_*DI];
__device__ float g_z  [B_*DI];              // z at l = L-1

// =============================================================================
// TF32 tensor-core GEMM (R2 layout, proven): C = epi(A@W + bias)
// A: MxK row-major (lda), W: KxN row-major (ldw), C: MxN (ldc)
// M % 128 == 0, K % 16 == 0.  Block tile 128x128, BK=16, double-buffered smem.
// 256 threads = 8 warps in 2(m) x 4(n), warp tile 64x32, mma m16n8k8.
// __launch_bounds__(256,2): clamp regs to 128 so 2 CTAs/SM fit (was 130 -> 1 CTA).
// =============================================================================
__device__ __forceinline__ uint32_t f2tf32(float f) {
    uint32_t u;
    asm volatile("cvt.rna.tf32.f32 %0, %1;" : "=r"(u) : "f"(f));
    return u;
}
__device__ __forceinline__ void mma_tf32(float* c, const uint32_t* a, const uint32_t* b) {
    asm volatile(
        "mma.sync.aligned.m16n8k8.row.col.f32.tf32.tf32.f32 "
        "{%0,%1,%2,%3}, {%4,%5,%6,%7}, {%8,%9}, {%0,%1,%2,%3};\n"
        : "+f"(c[0]), "+f"(c[1]), "+f"(c[2]), "+f"(c[3])
        : "r"(a[0]), "r"(a[1]), "r"(a[2]), "r"(a[3]), "r"(b[0]), "r"(b[1]));
}

#define SSTRIDE 136   // floats; 136 % 32 == 8 -> conflict-free fragment loads

template<int RELU>
__global__ __launch_bounds__(256, 2) void tgemm_kernel(
    const float* __restrict__ A, int lda,
    const float* __restrict__ W, int ldw,
    const float* __restrict__ bias,
    float* __restrict__ C, int ldc,
    int N, int K)
{
    __shared__ uint32_t As[2][16 * SSTRIDE];
    __shared__ uint32_t Bs[2][16 * SSTRIDE];

    const int bm = blockIdx.y * 128;
    const int bn = blockIdx.x * 128;
    const int tid = threadIdx.x;
    const int warp = tid >> 5;
    const int lane = tid & 31;
    const int warp_m = (warp & 1) * 64;
    const int warp_n = (warp >> 1) * 32;
    const int lg = lane >> 2;      // 0..7
    const int lr = lane & 3;       // 0..3

    // gmem load coords (per-thread, fixed across tiles)
    const int am0 = tid >> 2;            // A: element pair 0: m
    const int akq0 = tid & 3;            //               k-quad
    const int am1 = (tid + 256) >> 2;
    const int akq1 = (tid + 256) & 3;
    const int bk0 = tid >> 5;            // B: element pair 0
    const int bn40 = tid & 31;
    const int bk1 = (tid + 256) >> 5;
    const int bn41 = (tid + 256) & 31;

    float acc[4][4][4];
    #pragma unroll
    for (int i = 0; i < 4; i++)
        #pragma unroll
        for (int j = 0; j < 4; j++)
            #pragma unroll
            for (int r = 0; r < 4; r++) acc[i][j][r] = 0.f;

    const int T = K >> 4;

    float4 ar0, ar1, br0, br1;

    // ---- load tile 0 ----
    {
        const int k0 = 0;
        ar0 = *(const float4*)&A[(size_t)(bm + am0) * lda + k0 + akq0 * 4];
        ar1 = *(const float4*)&A[(size_t)(bm + am1) * lda + k0 + akq1 * 4];
        {
            int n = bn + bn40 * 4;
            const float* wr = W + (size_t)(k0 + bk0) * ldw;
            if (n + 3 < N) br0 = *(const float4*)&wr[n];
            else {
                br0.x = (n     < N) ? wr[n]     : 0.f;
                br0.y = (n + 1 < N) ? wr[n + 1] : 0.f;
                br0.z = (n + 2 < N) ? wr[n + 2] : 0.f;
                br0.w = (n + 3 < N) ? wr[n + 3] : 0.f;
            }
            n = bn + bn41 * 4;
            const float* wr1 = W + (size_t)(k0 + bk1) * ldw;
            if (n + 3 < N) br1 = *(const float4*)&wr1[n];
            else {
                br1.x = (n     < N) ? wr1[n]     : 0.f;
                br1.y = (n + 1 < N) ? wr1[n + 1] : 0.f;
                br1.z = (n + 2 < N) ? wr1[n + 2] : 0.f;
                br1.w = (n + 3 < N) ? wr1[n + 3] : 0.f;
            }
        }
        As[0][(akq0 * 4 + 0) * SSTRIDE + am0] = f2tf32(ar0.x);
        As[0][(akq0 * 4 + 1) * SSTRIDE + am0] = f2tf32(ar0.y);
        As[0][(akq0 * 4 + 2) * SSTRIDE + am0] = f2tf32(ar0.z);
        As[0][(akq0 * 4 + 3) * SSTRIDE + am0] = f2tf32(ar0.w);
        As[0][(akq1 * 4 + 0) * SSTRIDE + am1] = f2tf32(ar1.x);
        As[0][(akq1 * 4 + 1) * SSTRIDE + am1] = f2tf32(ar1.y);
        As[0][(akq1 * 4 + 2) * SSTRIDE + am1] = f2tf32(ar1.z);
        As[0][(akq1 * 4 + 3) * SSTRIDE + am1] = f2tf32(ar1.w);
        uint4 bu;
        bu.x = f2tf32(br0.x); bu.y = f2tf32(br0.y); bu.z = f2tf32(br0.z); bu.w = f2tf32(br0.w);
        *(uint4*)&Bs[0][bk0 * SSTRIDE + bn40 * 4] = bu;
        bu.x = f2tf32(br1.x); bu.y = f2tf32(br1.y); bu.z = f2tf32(br1.z); bu.w = f2tf32(br1.w);
        *(uint4*)&Bs[0][bk1 * SSTRIDE + bn41 * 4] = bu;
    }
    __syncthreads();

    for (int t = 0; t < T; t++) {
        const int s = t & 1;
        // prefetch next tile into registers
        if (t + 1 < T) {
            const int k0 = (t + 1) * 16;
            ar0 = *(const float4*)&A[(size_t)(bm + am0) * lda + k0 + akq0 * 4];
            ar1 = *(const float4*)&A[(size_t)(bm + am1) * lda + k0 + akq1 * 4];
            int n = bn + bn40 * 4;
            const float* wr = W + (size_t)(k0 + bk0) * ldw;
            if (n + 3 < N) br0 = *(const float4*)&wr[n];
            else {
                br0.x = (n     < N) ? wr[n]     : 0.f;
                br0.y = (n + 1 < N) ? wr[n + 1] : 0.f;
                br0.z = (n + 2 < N) ? wr[n + 2] : 0.f;
                br0.w = (n + 3 < N) ? wr[n + 3] : 0.f;
            }
            n = bn + bn41 * 4;
            const float* wr1 = W + (size_t)(k0 + bk1) * ldw;
            if (n + 3 < N) br1 = *(const float4*)&wr1[n];
            else {
                br1.x = (n     < N) ? wr1[n]     : 0.f;
                br1.y = (n + 1 < N) ? wr1[n + 1] : 0.f;
                br1.z = (n + 2 < N) ? wr1[n + 2] : 0.f;
                br1.w = (n + 3 < N) ? wr1[n + 3] : 0.f;
            }
        }
        // compute on stage s (two k8 steps)
        #pragma unroll
        for (int ks = 0; ks < 2; ks++) {
            const int k = ks * 8;
            uint32_t af[4][4], bf[4][2];
            #pragma unroll
            for (int mi = 0; mi < 4; mi++) {
                const int m0 = warp_m + mi * 16;
                af[mi][0] = As[s][(k + lr)     * SSTRIDE + m0 + lg];
                af[mi][1] = As[s][(k + lr)     * SSTRIDE + m0 + lg + 8];
                af[mi][2] = As[s][(k + 4 + lr) * SSTRIDE + m0 + lg];
                af[mi][3] = As[s][(k + 4 + lr) * SSTRIDE + m0 + lg + 8];
            }
            #pragma unroll
            for (int ni = 0; ni < 4; ni++) {
                const int n0 = warp_n + ni * 8;
                bf[ni][0] = Bs[s][(k + lr)     * SSTRIDE + n0 + lg];
                bf[ni][1] = Bs[s][(k + 4 + lr) * SSTRIDE + n0 + lg];
            }
            #pragma unroll
            for (int mi = 0; mi < 4; mi++)
                #pragma unroll
                for (int ni = 0; ni < 4; ni++)
                    mma_tf32(acc[mi][ni], af[mi], bf[ni]);
        }
        // store next tile (opposite stage; current stage still protected by loop-end sync)
        if (t + 1 < T) {
            const int sn = s ^ 1;
            As[sn][(akq0 * 4 + 0) * SSTRIDE + am0] = f2tf32(ar0.x);
            As[sn][(akq0 * 4 + 1) * SSTRIDE + am0] = f2tf32(ar0.y);
            As[sn][(akq0 * 4 + 2) * SSTRIDE + am0] = f2tf32(ar0.z);
            As[sn][(akq0 * 4 + 3) * SSTRIDE + am0] = f2tf32(ar0.w);
            As[sn][(akq1 * 4 + 0) * SSTRIDE + am1] = f2tf32(ar1.x);
            As[sn][(akq1 * 4 + 1) * SSTRIDE + am1] = f2tf32(ar1.y);
            As[sn][(akq1 * 4 + 2) * SSTRIDE + am1] = f2tf32(ar1.z);
            As[sn][(akq1 * 4 + 3) * SSTRIDE + am1] = f2tf32(ar1.w);
            uint4 bu;
            bu.x = f2tf32(br0.x); bu.y = f2tf32(br0.y); bu.z = f2tf32(br0.z); bu.w = f2tf32(br0.w);
            *(uint4*)&Bs[sn][bk0 * SSTRIDE + bn40 * 4] = bu;
            bu.x = f2tf32(br1.x); bu.y = f2tf32(br1.y); bu.z = f2tf32(br1.z); bu.w = f2tf32(br1.w);
            *(uint4*)&Bs[sn][bk1 * SSTRIDE + bn41 * 4] = bu;
        }
        __syncthreads();
    }

    // ---- epilogue ----
    #pragma unroll
    for (int mi = 0; mi < 4; mi++) {
        #pragma unroll
        for (int half = 0; half < 2; half++) {
            const int gr = bm + warp_m + mi * 16 + lg + half * 8;
            #pragma unroll
            for (int ni = 0; ni < 4; ni++) {
                const int gn = bn + warp_n + ni * 8 + lr * 2;
                if (gn >= N) continue;
                float v0 = acc[mi][ni][half * 2 + 0];
                float v1 = acc[mi][ni][half * 2 + 1];
                if (bias) { v0 += bias[gn]; v1 += bias[gn + 1]; }
                if (RELU) { v0 = fmaxf(v0, 0.f); v1 = fmaxf(v1, 0.f); }
                *(float2*)&C[(size_t)gr * ldc + gn] = make_float2(v0, v1);
            }
        }
    }
}

// ---------------- generic tiled SGEMM (tiny GEMMs) ----------------------------
template<int RELU>
__global__ void sgemm_kernel(const float* __restrict__ A, int lda,
                             const float* __restrict__ W, int ldw,
                             const float* __restrict__ bias,
                             float* __restrict__ C, int ldc,
                             int M, int N, int K)
{
    __shared__ float As[8][128];
    __shared__ float Bs[8][128];
    const int bm = blockIdx.y * 128;
    const int bn = blockIdx.x * 128;
    const int tid = threadIdx.x;
    const int tr = tid >> 4;
    const int tc = tid & 15;

    float acc[8][8];
    #pragma unroll
    for (int i = 0; i < 8; i++)
        #pragma unroll
        for (int j = 0; j < 8; j++) acc[i][j] = 0.f;

    for (int k0 = 0; k0 < K; k0 += 8) {
        {
            int e = tid * 4;
            int r = e >> 3, kk = e & 7;
            int gr = bm + r;
            float4 av = make_float4(0.f, 0.f, 0.f, 0.f);
            if (gr < M) av = *(const float4*)&A[(size_t)gr * lda + k0 + kk];
            As[kk + 0][r] = av.x; As[kk + 1][r] = av.y;
            As[kk + 2][r] = av.z; As[kk + 3][r] = av.w;
        }
        {
            int e = tid * 4;
            int kk = e >> 7, n = e & 127;
            const float* wrow = W + (size_t)(k0 + kk) * ldw;
            #pragma unroll
            for (int i = 0; i < 4; i++) {
                int gn = bn + n + i;
                Bs[kk][n + i] = (gn < N) ? wrow[gn] : 0.f;
            }
        }
        __syncthreads();
        #pragma unroll
        for (int kk = 0; kk < 8; kk++) {
            float4 a0 = *(const float4*)&As[kk][tr * 4];
            float4 a1 = *(const float4*)&As[kk][64 + tr * 4];
            float4 b0 = *(const float4*)&Bs[kk][tc * 4];
            float4 b1 = *(const float4*)&Bs[kk][64 + tc * 4];
            float a[8] = {a0.x,a0.y,a0.z,a0.w,a1.x,a1.y,a1.z,a1.w};
            float b[8] = {b0.x,b0.y,b0.z,b0.w,b1.x,b1.y,b1.z,b1.w};
            #pragma unroll
            for (int i = 0; i < 8; i++)
                #pragma unroll
                for (int j = 0; j < 8; j++) acc[i][j] = fmaf(a[i], b[j], acc[i][j]);
        }
        __syncthreads();
    }
    #pragma unroll
    for (int i = 0; i < 8; i++) {
        int gr = bm + ((i < 4) ? (tr * 4 + i) : (64 + tr * 4 + i - 4));
        if (gr >= M) continue;
        #pragma unroll
        for (int j = 0; j < 8; j++) {
            int gn = bn + ((j < 4) ? (tc * 4 + j) : (64 + tc * 4 + j - 4));
            if (gn >= N) continue;
            float v = acc[i][j];
            if (bias) v += bias[gn];
            if (RELU) v = fmaxf(v, 0.f);
            C[(size_t)gr * ldc + gn] = v;
        }
    }
}

// ---------------- depthwise causal conv (time-marching) + silu + softplus -----
__device__ __forceinline__ float siluf(float x) { return x / (1.f + __expf(-x)); }
__device__ __forceinline__ float softplusf(float x) {
    return (x > 0.f) ? x + log1pf(__expf(-x)) : log1pf(__expf(x));
}

#define LCH 128   // time chunk per block-z

__global__ void conv_kernel(const float* __restrict__ xbcr,   // [BL, REST]
                            const float* __restrict__ conv_w, // [1152,4]
                            const float* __restrict__ conv_b, // [1152]
                            const float* __restrict__ dt_bias,// [16]
                            float* __restrict__ xs, float* __restrict__ Bm,
                            float* __restrict__ Cm, float* __restrict__ dtp)
{
    int c  = blockIdx.x * blockDim.x + threadIdx.x;
    int b  = blockIdx.y;
    int l0 = blockIdx.z * LCH;
    if (c >= REST) return;
    const float* col = xbcr + (size_t)b * L_ * REST + c;

    if (c >= CONV_DIM) {
        int h = c - CONV_DIM;
        float bias = dt_bias[h];
        float* drow = dtp + (size_t)(b * H_ + h) * L_;
        #pragma unroll 4
        for (int l = l0; l < l0 + LCH; l++)
            drow[l] = softplusf(col[(size_t)l * REST] + bias);
        return;
    }

    float w0 = conv_w[c * 4 + 0], w1 = conv_w[c * 4 + 1];
    float w2 = conv_w[c * 4 + 2], w3 = conv_w[c * 4 + 3];
    float cb = conv_b[c];

    if (c >= DI + N_) {
        if (l0 + LCH != L_) return;
        int l = L_ - 1;
        float acc = cb + w0 * col[(size_t)(l - 3) * REST] + w1 * col[(size_t)(l - 2) * REST]
                       + w2 * col[(size_t)(l - 1) * REST] + w3 * col[(size_t)l * REST];
        Cm[b * N_ + (c - DI - N_)] = siluf(acc);
        return;
    }

    float xm3 = (l0 - 3 >= 0) ? col[(size_t)(l0 - 3) * REST] : 0.f;
    float xm2 = (l0 - 2 >= 0) ? col[(size_t)(l0 - 2) * REST] : 0.f;
    float xm1 = (l0 - 1 >= 0) ? col[(size_t)(l0 - 1) * REST] : 0.f;
    if (c < DI) {
        float* orow = xs + (size_t)(b * L_ + l0) * DI + c;
        #pragma unroll 4
        for (int l = l0; l < l0 + LCH; l++) {
            float xl = col[(size_t)l * REST];
            float acc = fmaf(w0, xm3, fmaf(w1, xm2, fmaf(w2, xm1, fmaf(w3, xl, cb))));
            *orow = siluf(acc);
            orow += DI;
            xm3 = xm2; xm2 = xm1; xm1 = xl;
        }
    } else {
        float* orow = Bm + (size_t)(b * L_ + l0) * N_ + (c - DI);
        #pragma unroll 4
        for (int l = l0; l < l0 + LCH; l++) {
            float xl = col[(size_t)l * REST];
            float acc = fmaf(w0, xm3, fmaf(w1, xm2, fmaf(w2, xm1, fmaf(w3, xl, cb))));
            *orow = siluf(acc);
            orow += N_;
            xm3 = xm2; xm2 = xm1; xm1 = xl;
        }
    }
}

// ---------------- suffix-sum of dt and coefficient exp(-a*S)*dt ---------------
__global__ void scan_kernel(const float* __restrict__ dtp,
                            const float* __restrict__ A_log,
                            float* __restrict__ coef)
{
    int bh = blockIdx.x;
    int h = bh & (H_ - 1);
    float a = expf(A_log[h]);
    __shared__ float part[256];
    __shared__ float off[256];
    const float* row = dtp + (size_t)bh * L_;
    int t0 = threadIdx.x * 4;
    float v0 = row[t0], v1 = row[t0 + 1], v2 = row[t0 + 2], v3 = row[t0 + 3];
    part[threadIdx.x] = v0 + v1 + v2 + v3;
    __syncthreads();
    if (threadIdx.x == 0) {
        float s = 0.f;
        for (int i = 255; i >= 0; i--) { off[i] = s; s += part[i]; }
    }
    __syncthreads();
    float S3 = off[threadIdx.x];
    float S2 = S3 + v3;
    float S1 = S2 + v2;
    float S0 = S1 + v1;
    float* out = coef + (size_t)bh * L_;
    out[t0 + 0] = expf(-a * S0) * v0;
    out[t0 + 1] = expf(-a * S1) * v1;
    out[t0 + 2] = expf(-a * S2) * v2;
    out[t0 + 3] = expf(-a * S3) * v3;
}

// ---------------- beta[b,t] = B_t . C_last -----------------------------------
__global__ void beta_kernel(const float* __restrict__ Bm,
                            const float* __restrict__ Cm,
                            float* __restrict__ beta)
{
    int row = blockIdx.x;
    int b = row >> 10;
    int lane = threadIdx.x;
    float s = Bm[(size_t)row * N_ + lane]      * Cm[b * N_ + lane]
            + Bm[(size_t)row * N_ + 32 + lane] * Cm[b * N_ + 32 + lane];
    #pragma unroll
    for (int o = 16; o; o >>= 1) s += __shfl_down_sync(0xffffffffu, s, o);
    if (lane == 0) beta[row] = s;
}

// ---------------- y[b,h,p] = sum_t coef*beta*xs + D*xs_last -------------------
__global__ void y_kernel(const float* __restrict__ xs,
                         const float* __restrict__ coef,
                         const float* __restrict__ beta,
                         const float* __restrict__ D,
                         float* __restrict__ y)
{
    int bh = blockIdx.x;
    int b = bh >> 4, h = bh & (H_ - 1);
    int tid = threadIdx.x;                // 512 threads
    int tq = tid >> 6;
    int p  = tid & 63;
    __shared__ float w[L_];
    __shared__ float partial[8][64];
    const float* crow = coef + (size_t)bh * L_;
    const float* brow = beta + (size_t)b * L_;
    for (int i = tid; i < L_; i += 512) w[i] = crow[i] * brow[i];
    __syncthreads();
    const float* xbase = xs + (size_t)b * L_ * DI + h * P_ + p;
    float acc = 0.f;
    const int t0 = tq * 128;
    #pragma unroll 4
    for (int t = t0; t < t0 + 128; t++)
        acc = fmaf(w[t], xbase[(size_t)t * DI], acc);
    partial[tq][p] = acc;
    __syncthreads();
    if (tq == 0) {
        float s = 0.f;
        #pragma unroll
        for (int q = 0; q < 8; q++) s += partial[q][p];
        s = fmaf(D[h], xbase[(size_t)(L_ - 1) * DI], s);
        y[bh * P_ + p] = s;
    }
}

// ---------------- gate + rmsnorm + Wout + Wc head -----------------------------
__global__ void final_kernel(const float* __restrict__ y,
                             const float* __restrict__ zlast,
                             const float* __restrict__ norm_w,
                             const float* __restrict__ Wout,
                             const float* __restrict__ Wc,
                             const float* __restrict__ bc,
                             float* __restrict__ out)
{
    int b = blockIdx.x;
    int tid = threadIdx.x;                // 256
    __shared__ float yn[DI];
    __shared__ float seq[DM];
    __shared__ float red[256];
    float ss = 0.f;
    for (int d = tid; d < DI; d += 256) {
        float z = zlast[b * DI + d];
        float g = y[b * DI + d] * (z / (1.f + __expf(-z)));
        yn[d] = g;
        ss += g * g;
    }
    red[tid] = ss; __syncthreads();
    for (int o = 128; o; o >>= 1) { if (tid < o) red[tid] += red[tid + o]; __syncthreads(); }
    float scale = rsqrtf(red[0] / (float)DI + EPS);
    for (int d = tid; d < DI; d += 256) yn[d] *= scale * norm_w[d];
    __syncthreads();
    for (int m = tid; m < DM; m += 256) {
        float accm = 0.f;
        for (int d = 0; d < DI; d++) accm = fmaf(yn[d], Wout[(size_t)d * DM + m], accm);
        seq[m] = accm;
    }
    __syncthreads();
    if (tid < NCLS) {
        float acc = bc[tid];
        for (int m = 0; m < DM; m++) acc = fmaf(seq[m], Wc[m * NCLS + tid], acc);
        out[b * NCLS + tid] = acc;
    }
}

// ---------------- launch ------------------------------------------------------
extern "C" void kernel_launch(void* const* d_in, const int* in_sizes, int n_in,
                              void* d_out, int out_size)
{
    const float* x       = (const float*)d_in[0];
    const float* W1      = (const float*)d_in[1];
    const float* b1      = (const float*)d_in[2];
    const float* W2      = (const float*)d_in[3];
    const float* b2      = (const float*)d_in[4];
    const float* W3      = (const float*)d_in[5];
    const float* b3      = (const float*)d_in[6];
    const float* Win     = (const float*)d_in[7];
    const float* conv_w  = (const float*)d_in[8];
    const float* conv_b  = (const float*)d_in[9];
    const float* dt_bias = (const float*)d_in[10];
    const float* A_log   = (const float*)d_in[11];
    const float* Dv      = (const float*)d_in[12];
    const float* norm_w  = (const float*)d_in[13];
    const float* Wout    = (const float*)d_in[14];
    const float* Wc      = (const float*)d_in[15];
    const float* bc      = (const float*)d_in[16];
    float* out = (float*)d_out;

    float *h1, *h2, *u, *xbcr, *xs, *Bm, *Cm, *dtp, *coef, *beta, *yb, *zb;
    cudaGetSymbolAddress((void**)&h1,   g_h1);
    cudaGetSymbolAddress((void**)&h2,   g_h2);
    cudaGetSymbolAddress((void**)&u,    g_u);
    cudaGetSymbolAddress((void**)&xbcr, g_xbcr);
    cudaGetSymbolAddress((void**)&xs,   g_xs);
    cudaGetSymbolAddress((void**)&Bm,   g_Bm);
    cudaGetSymbolAddress((void**)&Cm,   g_Cm);
    cudaGetSymbolAddress((void**)&dtp,  g_dtp);
    cudaGetSymbolAddress((void**)&coef, g_coef);
    cudaGetSymbolAddress((void**)&beta, g_beta);
    cudaGetSymbolAddress((void**)&yb,   g_y);
    cudaGetSymbolAddress((void**)&zb,   g_z);

    // G1: x -> 128 (K=16, fp32 fma)
    sgemm_kernel<1><<<dim3(1, BL/128), 256>>>(x, DIN, W1, 128, b1, h1, 128, BL, 128, DIN);
    // G2: 128 -> 256 (tf32)
    tgemm_kernel<1><<<dim3(2, BL/128), 256>>>(h1, 128, W2, 256, b2, h2, 256, 256, 128);
    // G3: 256 -> 512 (tf32)
    tgemm_kernel<0><<<dim3(4, BL/128), 256>>>(h2, 256, W3, DM, b3, u, DM, DM, 256);
    // G4: u @ Win[:, DI:DPROJ] (tf32), N=1168
    tgemm_kernel<0><<<dim3(10, BL/128), 256>>>(u, DM, Win + DI, DPROJ, nullptr,
                                               xbcr, REST, REST, DM);
    // G5: z at last position only (32 rows, fp32)
    sgemm_kernel<0><<<dim3(DI/128, 1), 256>>>(u + (size_t)(L_-1)*DM, L_*DM, Win, DPROJ, nullptr,
                                              zb, DI, B_, DI, DM);
    // conv + silu + softplus(dt), time-marching
    conv_kernel<<<dim3((REST+255)/256, B_, L_/LCH), 256>>>(xbcr, conv_w, conv_b, dt_bias,
                                                           xs, Bm, Cm, dtp);
    // suffix scan -> coefficients
    scan_kernel<<<B_*H_, 256>>>(dtp, A_log, coef);
    // beta
    beta_kernel<<<BL, 32>>>(Bm, Cm, beta);
    // y reduction over time
    y_kernel<<<B_*H_, 512>>>(xs, coef, beta, Dv, yb);
    // head
    final_kernel<<<B_, 256>>>(yb, zb, norm_w, Wout, Wc, bc, out);
    (void)in_sizes; (void)n_in; (void)out_size;
}